// round 4
// baseline (speedup 1.0000x reference)
#include <cuda_runtime.h>
#include <cuda_bf16.h>
#include <cstdint>

#define N 4096
#define D 512
#define ITERS 50
#define REG 0.05f
#define INV_REG 20.0f
#define EPS 1e-9f
#define AB (1.0f/4096.0f)

#define BLOCKS_UV 128
#define ROWS_PER_BLOCK (N / BLOCKS_UV)   // 32
#define RG 4                              // rows per group (prefetch depth)

// -------- scratch (device globals: allocation-free contract) --------
__device__ __nv_bfloat16 g_K[(size_t)N * N];        // 32 MB bf16 kernel matrix
__device__ float         g_u[N];
__device__ float         g_v[N];
__device__ float         g_vpart[BLOCKS_UV * N];    // 2 MB partials (deterministic)
__device__ float         g_Xs[N];
__device__ float         g_Ys[N];
__device__ float         g_losspart[N];
__device__ unsigned      g_bar_count;
__device__ unsigned      g_bar_gen;

// -------- helpers --------
__device__ __forceinline__ float blockReduceSum(float val) {
    __shared__ float sh[32];
    int lane = threadIdx.x & 31;
    int wid  = threadIdx.x >> 5;
#pragma unroll
    for (int o = 16; o; o >>= 1) val += __shfl_down_sync(0xffffffffu, val, o);
    if (lane == 0) sh[wid] = val;
    __syncthreads();
    int nw = (blockDim.x + 31) >> 5;
    val = (threadIdx.x < nw) ? sh[threadIdx.x] : 0.0f;
    if (wid == 0) {
#pragma unroll
        for (int o = 16; o; o >>= 1) val += __shfl_down_sync(0xffffffffu, val, o);
    }
    return val;  // valid in thread 0
}

// bf16x2 word -> packed f32x2 (lo half = even col, hi half = odd col)
__device__ __forceinline__ unsigned long long bf2_f32x2(unsigned w) {
    unsigned lo = w << 16;
    unsigned hi = w & 0xffff0000u;
    unsigned long long d;
    asm("mov.b64 %0, {%1, %2};" : "=l"(d) : "r"(lo), "r"(hi));
    return d;
}

// software grid barrier (classic count+generation, self-resetting)
__device__ __forceinline__ void grid_barrier() {
    __threadfence();          // make this block's writes visible at L2
    __syncthreads();
    if (threadIdx.x == 0) {
        unsigned gen = *((volatile unsigned*)&g_bar_gen);
        unsigned old = atomicAdd(&g_bar_count, 1u);
        if (old == BLOCKS_UV - 1) {
            g_bar_count = 0;                 // all arrived; safe to reset
            __threadfence();
            atomicAdd(&g_bar_gen, 1u);       // release
        } else {
            while (*((volatile unsigned*)&g_bar_gen) == gen) __nanosleep(32);
        }
        __threadfence();      // acquire: order subsequent reads
    }
    __syncthreads();
}

// -------- kernel 1: row norms of X and Y, v <- 1, barrier reset --------
__global__ void norms_init_kernel(const float* __restrict__ X,
                                  const float* __restrict__ Y) {
    int row = blockIdx.x;  // 0..8191
    if (row == 0 && threadIdx.x == 0) { g_bar_count = 0; }
    const float* src = (row < N) ? (X + (size_t)row * D)
                                 : (Y + (size_t)(row - N) * D);
    float4 t = ((const float4*)src)[threadIdx.x];  // 128 threads * 4 = 512
    float s = t.x * t.x + t.y * t.y + t.z * t.z + t.w * t.w;
    s = blockReduceSum(s);
    if (threadIdx.x == 0) {
        if (row < N) g_Xs[row] = s;
        else         g_Ys[row - N] = s;
    }
    if (row < 32) g_v[row * 128 + threadIdx.x] = 1.0f;
}

// -------- kernel 2: K GEMM (128x128 tile, f32x2 packed FMA) --------
__global__ void __launch_bounds__(256)
cost_gemm_kernel(const float* __restrict__ X, const float* __restrict__ Y) {
    __shared__ float As[16][128];
    __shared__ float Bs[16][128];
    int tid = threadIdx.x;
    int tx = tid & 15, ty = tid >> 4;
    int bm = blockIdx.y * 128, bn = blockIdx.x * 128;

    unsigned long long acc[8][4];
#pragma unroll
    for (int i = 0; i < 8; i++)
#pragma unroll
        for (int j = 0; j < 4; j++) acc[i][j] = 0ULL;

    for (int kk = 0; kk < D; kk += 16) {
#pragma unroll
        for (int p = 0; p < 2; p++) {
            int idx = tid + p * 256;
            int row = idx & 127;
            int kq  = idx >> 7;
            float4 av = *(const float4*)(X + (size_t)(bm + row) * D + kk + kq * 4);
            As[kq * 4 + 0][row] = av.x;
            As[kq * 4 + 1][row] = av.y;
            As[kq * 4 + 2][row] = av.z;
            As[kq * 4 + 3][row] = av.w;
            float4 bv = *(const float4*)(Y + (size_t)(bn + row) * D + kk + kq * 4);
            Bs[kq * 4 + 0][row] = bv.x;
            Bs[kq * 4 + 1][row] = bv.y;
            Bs[kq * 4 + 2][row] = bv.z;
            Bs[kq * 4 + 3][row] = bv.w;
        }
        __syncthreads();
#pragma unroll
        for (int k = 0; k < 16; k++) {
            float4 a0 = *(const float4*)&As[k][ty * 4];
            float4 a1 = *(const float4*)&As[k][64 + ty * 4];
            float4 b0 = *(const float4*)&Bs[k][tx * 4];
            float4 b1 = *(const float4*)&Bs[k][64 + tx * 4];
            unsigned long long bb[4];
            bb[0] = ((const unsigned long long*)&b0)[0];
            bb[1] = ((const unsigned long long*)&b0)[1];
            bb[2] = ((const unsigned long long*)&b1)[0];
            bb[3] = ((const unsigned long long*)&b1)[1];
            float am[8] = {a0.x, a0.y, a0.z, a0.w, a1.x, a1.y, a1.z, a1.w};
#pragma unroll
            for (int m = 0; m < 8; m++) {
                unsigned long long a2;
                asm("mov.b64 %0, {%1, %1};" : "=l"(a2) : "f"(am[m]));
#pragma unroll
                for (int n2 = 0; n2 < 4; n2++) {
                    asm("fma.rn.f32x2 %0, %1, %2, %0;"
                        : "+l"(acc[m][n2]) : "l"(a2), "l"(bb[n2]));
                }
            }
        }
        __syncthreads();
    }

#pragma unroll
    for (int m = 0; m < 8; m++) {
        int row = bm + ((m < 4) ? (ty * 4 + m) : (64 + ty * 4 + (m - 4)));
        float xs = g_Xs[row];
#pragma unroll
        for (int half = 0; half < 2; half++) {
            int col = bn + ((half == 0) ? (tx * 4) : (64 + tx * 4));
            float c[4];
#pragma unroll
            for (int q = 0; q < 2; q++) {
                float2 pr = *(float2*)&acc[m][half * 2 + q];
                c[q * 2 + 0] = pr.x;
                c[q * 2 + 1] = pr.y;
            }
            float kf[4];
#pragma unroll
            for (int q = 0; q < 4; q++) {
                float cost = xs + g_Ys[col + q] - 2.0f * c[q];
                cost = fmaxf(cost, 0.0f);
                kf[q] = expf(-cost * INV_REG);
            }
            __nv_bfloat162 p0 = __floats2bfloat162_rn(kf[0], kf[1]);
            __nv_bfloat162 p1 = __floats2bfloat162_rn(kf[2], kf[3]);
            *(__nv_bfloat162*)(g_K + (size_t)row * N + col)     = p0;
            *(__nv_bfloat162*)(g_K + (size_t)row * N + col + 2) = p1;
        }
    }
}

// -------- kernel 3: PERSISTENT Sinkhorn loop (packed f32x2 math) --------
// Phase A: block b handles rows [b*32, +32): u_i = a/(K_i.v + eps),
//          vp accumulated as f32x2; each K value converted exactly ONCE.
// Phase B: block b reduces partials for columns [b*32, +32) -> v_j.
__global__ void __launch_bounds__(256) sinkhorn_kernel() {
    __shared__ float red[RG][8];
    __shared__ float ush[RG];
    __shared__ float vred[8][32];
    int tid  = threadIdx.x;
    int lane = tid & 31, wid = tid >> 5;
    int base = blockIdx.x * ROWS_PER_BLOCK;

    for (int it = 0; it < ITERS; ++it) {
        // ---- Phase A ----
        unsigned long long vlk[8];      // packed v for owned 16 cols
        const unsigned long long* vg = (const unsigned long long*)g_v;
#pragma unroll
        for (int q = 0; q < 8; q++) vlk[q] = __ldcg(&vg[tid * 8 + q]);

        unsigned long long vpk[8];      // packed vp accumulators
#pragma unroll
        for (int q = 0; q < 8; q++) vpk[q] = 0ULL;

        uint4 raw[RG][2];               // raw prefetch buffer
        unsigned long long fc[RG][8];   // converted current group
#pragma unroll
        for (int r = 0; r < RG; r++) {
            const uint4* kr = (const uint4*)(g_K + (size_t)(base + r) * N);
            raw[r][0] = __ldg(&kr[2 * tid]);
            raw[r][1] = __ldg(&kr[2 * tid + 1]);
        }
#pragma unroll
        for (int r = 0; r < RG; r++) {
            const unsigned* w = (const unsigned*)&raw[r][0];
#pragma unroll
            for (int q = 0; q < 8; q++) fc[r][q] = bf2_f32x2(w[q]);
        }

        for (int g0 = 0; g0 < ROWS_PER_BLOCK; g0 += RG) {
            // prefetch next raw group (overlaps L2 latency with compute)
            if (g0 + RG < ROWS_PER_BLOCK) {
#pragma unroll
                for (int r = 0; r < RG; r++) {
                    const uint4* kr = (const uint4*)(g_K + (size_t)(base + g0 + RG + r) * N);
                    raw[r][0] = __ldg(&kr[2 * tid]);
                    raw[r][1] = __ldg(&kr[2 * tid + 1]);
                }
            }
            // packed dots
            float dot[RG];
#pragma unroll
            for (int r = 0; r < RG; r++) {
                unsigned long long dacc = 0ULL;
#pragma unroll
                for (int q = 0; q < 8; q++) {
                    asm("fma.rn.f32x2 %0, %1, %2, %0;"
                        : "+l"(dacc) : "l"(fc[r][q]), "l"(vlk[q]));
                }
                float dlo, dhi;
                asm("mov.b64 {%0, %1}, %2;" : "=f"(dlo), "=f"(dhi) : "l"(dacc));
                dot[r] = dlo + dhi;
            }
#pragma unroll
            for (int r = 0; r < RG; r++) {
                float s = dot[r];
#pragma unroll
                for (int o = 16; o; o >>= 1) s += __shfl_down_sync(0xffffffffu, s, o);
                if (lane == 0) red[r][wid] = s;
            }
            __syncthreads();
            if (tid < RG) {
                float s = 0.0f;
#pragma unroll
                for (int w = 0; w < 8; w++) s += red[tid][w];
                float u = AB / (s + EPS);
                ush[tid] = u;
                g_u[base + g0 + tid] = u;
            }
            __syncthreads();
            // packed vp accumulation (reuses converted fc)
#pragma unroll
            for (int r = 0; r < RG; r++) {
                unsigned long long u2;
                asm("mov.b64 %0, {%1, %1};" : "=l"(u2) : "f"(ush[r]));
#pragma unroll
                for (int q = 0; q < 8; q++) {
                    asm("fma.rn.f32x2 %0, %1, %2, %0;"
                        : "+l"(vpk[q]) : "l"(fc[r][q]), "l"(u2));
                }
            }
            // convert the prefetched raw group for next pass
            if (g0 + RG < ROWS_PER_BLOCK) {
#pragma unroll
                for (int r = 0; r < RG; r++) {
                    const unsigned* w = (const unsigned*)&raw[r][0];
#pragma unroll
                    for (int q = 0; q < 8; q++) fc[r][q] = bf2_f32x2(w[q]);
                }
            }
        }
        // write deterministic per-block partials (bit layout matches floats)
        unsigned long long* pp =
            (unsigned long long*)(g_vpart + (size_t)blockIdx.x * N + tid * 16);
#pragma unroll
        for (int q = 0; q < 8; q++) pp[q] = vpk[q];

        grid_barrier();

        // ---- Phase B: v for columns [blockIdx.x*32, +32) ----
        {
            int jj = tid & 31, bg = tid >> 5;      // 8 groups x 32 cols
            int j = blockIdx.x * 32 + jj;
            float s = 0.0f;
#pragma unroll
            for (int k = 0; k < BLOCKS_UV / 8; k++) {  // 16 partials per thread
                int b = bg * (BLOCKS_UV / 8) + k;
                s += __ldcg(&g_vpart[(size_t)b * N + j]);
            }
            vred[bg][jj] = s;
            __syncthreads();
            if (tid < 32) {
                float t = 0.0f;
#pragma unroll
                for (int w = 0; w < 8; w++) t += vred[w][tid];
                g_v[blockIdx.x * 32 + tid] = AB / (t + EPS);
            }
        }

        grid_barrier();
    }
}

// -------- kernel 4: per-row loss partials: sum_j u_i K_ij v_j cost_ij ----
// cost recovered from K: cost = max(-REG * ln(K), 0)
__global__ void __launch_bounds__(256) loss_part_kernel() {
    int i = blockIdx.x, tid = threadIdx.x;
    float ui = g_u[i];
    const uint4*  krow = (const uint4*)(g_K + (size_t)i * N);
    const float2* vv   = (const float2*)g_v;
    float s = 0.0f;
#pragma unroll
    for (int half = 0; half < 2; half++) {
        int q = half * 256 + tid;
        uint4 kb = krow[q];
        float2 f0 = __bfloat1622float2(*(__nv_bfloat162*)&kb.x);
        float2 f1 = __bfloat1622float2(*(__nv_bfloat162*)&kb.y);
        float2 f2 = __bfloat1622float2(*(__nv_bfloat162*)&kb.z);
        float2 f3 = __bfloat1622float2(*(__nv_bfloat162*)&kb.w);
        int j2 = q * 4;
        float2 v0 = vv[j2], v1 = vv[j2 + 1], v2 = vv[j2 + 2], v3 = vv[j2 + 3];
        float kf[8] = {f0.x, f0.y, f1.x, f1.y, f2.x, f2.y, f3.x, f3.y};
        float vf[8] = {v0.x, v0.y, v1.x, v1.y, v2.x, v2.y, v3.x, v3.y};
#pragma unroll
        for (int e = 0; e < 8; e++) {
            float cost = fmaxf(-REG * __logf(kf[e]), 0.0f);
            s += kf[e] * vf[e] * cost;
        }
    }
    s = blockReduceSum(s);
    if (tid == 0) g_losspart[i] = ui * s;
}

// -------- kernel 5: final deterministic reduction --------
__global__ void loss_fin_kernel(float* __restrict__ out) {
    float s = 0.0f;
    for (int i = threadIdx.x; i < N; i += 256) s += g_losspart[i];
    s = blockReduceSum(s);
    if (threadIdx.x == 0) out[0] = s;
}

// -------- launch --------
extern "C" void kernel_launch(void* const* d_in, const int* in_sizes, int n_in,
                              void* d_out, int out_size) {
    const float* X = (const float*)d_in[0];  // audio_features [4096,512]
    const float* Y = (const float*)d_in[1];  // text_features  [4096,512]
    float* out = (float*)d_out;

    norms_init_kernel<<<2 * N, 128>>>(X, Y);
    cost_gemm_kernel<<<dim3(32, 32), 256>>>(X, Y);
    sinkhorn_kernel<<<BLOCKS_UV, 256>>>();
    loss_part_kernel<<<N, 256>>>();
    loss_fin_kernel<<<1, 256>>>(out);
}

// round 6
// speedup vs baseline: 1.3821x; 1.3821x over previous
#include <cuda_runtime.h>
#include <cuda_bf16.h>
#include <cstdint>

#define N 4096
#define D 512
#define ITERS 50
#define REG 0.05f
#define INV_REG 20.0f
#define EPS 1e-9f
#define AB (1.0f/4096.0f)

#define BLOCKS_UV 128
#define ROWS_PER_BLOCK (N / BLOCKS_UV)   // 32
#define RG 4                              // rows per group (prefetch depth)

// -------- scratch (device globals: allocation-free contract) --------
__device__ __nv_bfloat16 g_K[(size_t)N * N];        // 32 MB bf16 kernel matrix
__device__ __nv_bfloat16 g_Xb[(size_t)N * D];       // 4 MB bf16 X
__device__ __nv_bfloat16 g_Yb[(size_t)N * D];       // 4 MB bf16 Y
__device__ float         g_u[N];
__device__ float         g_v[N];
__device__ float         g_vpart[BLOCKS_UV * N];    // 2 MB partials (deterministic)
__device__ float         g_Xs[N];
__device__ float         g_Ys[N];
__device__ float         g_losspart[N];
__device__ unsigned      g_bar_count;
__device__ unsigned      g_bar_gen;

// -------- helpers --------
#define SW128(b) ((b) ^ (((b) >> 3) & 0x70))

__device__ __forceinline__ uint32_t smem_u32(const void* p) {
    uint32_t a;
    asm("{ .reg .u64 t; cvta.to.shared.u64 t, %1; cvt.u32.u64 %0, t; }"
        : "=r"(a) : "l"(p));
    return a;
}

__device__ __forceinline__ void ldsm_x4(uint32_t addr, uint32_t& r0, uint32_t& r1,
                                        uint32_t& r2, uint32_t& r3) {
    asm volatile("ldmatrix.sync.aligned.m8n8.x4.shared.b16 {%0,%1,%2,%3}, [%4];"
                 : "=r"(r0), "=r"(r1), "=r"(r2), "=r"(r3) : "r"(addr));
}

__device__ __forceinline__ void mma_16816(float* c, const uint32_t* a,
                                          uint32_t b0, uint32_t b1) {
    asm volatile(
        "mma.sync.aligned.m16n8k16.row.col.f32.bf16.bf16.f32 "
        "{%0,%1,%2,%3}, {%4,%5,%6,%7}, {%8,%9}, {%0,%1,%2,%3};"
        : "+f"(c[0]), "+f"(c[1]), "+f"(c[2]), "+f"(c[3])
        : "r"(a[0]), "r"(a[1]), "r"(a[2]), "r"(a[3]), "r"(b0), "r"(b1));
}

__device__ __forceinline__ float blockReduceSum(float val) {
    __shared__ float sh[32];
    int lane = threadIdx.x & 31;
    int wid  = threadIdx.x >> 5;
#pragma unroll
    for (int o = 16; o; o >>= 1) val += __shfl_down_sync(0xffffffffu, val, o);
    if (lane == 0) sh[wid] = val;
    __syncthreads();
    int nw = (blockDim.x + 31) >> 5;
    val = (threadIdx.x < nw) ? sh[threadIdx.x] : 0.0f;
    if (wid == 0) {
#pragma unroll
        for (int o = 16; o; o >>= 1) val += __shfl_down_sync(0xffffffffu, val, o);
    }
    return val;
}

__device__ __forceinline__ unsigned long long bf2_f32x2(unsigned w) {
    unsigned lo = w << 16;
    unsigned hi = w & 0xffff0000u;
    unsigned long long d;
    asm("mov.b64 %0, {%1, %2};" : "=l"(d) : "r"(lo), "r"(hi));
    return d;
}

__device__ __forceinline__ void grid_barrier() {
    __threadfence();
    __syncthreads();
    if (threadIdx.x == 0) {
        unsigned gen = *((volatile unsigned*)&g_bar_gen);
        unsigned old = atomicAdd(&g_bar_count, 1u);
        if (old == BLOCKS_UV - 1) {
            g_bar_count = 0;
            __threadfence();
            atomicAdd(&g_bar_gen, 1u);
        } else {
            while (*((volatile unsigned*)&g_bar_gen) == gen) __nanosleep(32);
        }
        __threadfence();
    }
    __syncthreads();
}

// -------- kernel 1: norms + bf16 conversion + v<-1 + barrier reset --------
__global__ void norms_init_kernel(const float* __restrict__ X,
                                  const float* __restrict__ Y) {
    int row = blockIdx.x;  // 0..8191
    if (row == 0 && threadIdx.x == 0) { g_bar_count = 0; }
    bool isX = (row < N);
    int r = isX ? row : row - N;
    const float* src = isX ? (X + (size_t)r * D) : (Y + (size_t)r * D);
    float4 t = ((const float4*)src)[threadIdx.x];  // 128 thr * 4 = 512
    __nv_bfloat162 b0 = __floats2bfloat162_rn(t.x, t.y);
    __nv_bfloat162 b1 = __floats2bfloat162_rn(t.z, t.w);
    __nv_bfloat16* dst = isX ? g_Xb : g_Yb;
    uint2 packed = make_uint2(*(unsigned*)&b0, *(unsigned*)&b1);
    *(uint2*)(dst + (size_t)r * D + threadIdx.x * 4) = packed;
    float s = t.x * t.x + t.y * t.y + t.z * t.z + t.w * t.w;
    s = blockReduceSum(s);
    if (threadIdx.x == 0) {
        if (isX) g_Xs[r] = s;
        else     g_Ys[r] = s;
    }
    if (row < 32) g_v[row * 128 + threadIdx.x] = 1.0f;
}

// -------- kernel 2: bf16 HMMA GEMM -> K = exp(-cost/REG) --------
// Block tile 128x128, 8 warps as 4(M) x 2(N); warp tile 32x64.
// mma.sync m16n8k16 .row.col: A frags from X rows, B frags from Y rows
// (X.Y^T), both via plain ldmatrix.x4 on SW128-swizzled smem.
__global__ void __launch_bounds__(256)
k_gemm_kernel() {
    __shared__ __align__(1024) unsigned char sA[128 * 128];  // 128 rows x 64 bf16
    __shared__ __align__(1024) unsigned char sB[128 * 128];
    __shared__ float s_ys[128];
    __shared__ float s_xs[128];

    int tid = threadIdx.x;
    int lane = tid & 31, w = tid >> 5;
    int wm = w & 3, wn = w >> 2;          // warp coords: 4 x 2
    int bm = blockIdx.y * 128, bn = blockIdx.x * 128;

    if (tid < 128) s_ys[tid] = g_Ys[bn + tid];
    else           s_xs[tid - 128] = g_Xs[bm + tid - 128];

    uint32_t sA_base = smem_u32(sA);
    uint32_t sB_base = smem_u32(sB);

    float acc[2][8][4];
#pragma unroll
    for (int mt = 0; mt < 2; mt++)
#pragma unroll
        for (int nt = 0; nt < 8; nt++)
#pragma unroll
            for (int q = 0; q < 4; q++) acc[mt][nt][q] = 0.0f;

    // per-lane ldmatrix row/segment patterns (fixed per thread)
    int aRow = wm * 32 + (lane & 15);            // + mt*16
    int aSeg = (lane >> 4) & 1;
    int bRow = wn * 64 + (lane & 7) + ((lane >> 4) & 1) * 8;   // + np*16
    int bSeg = (lane >> 3) & 1;

    for (int kc = 0; kc < 8; kc++) {             // 8 chunks of K=64
        if (kc) __syncthreads();
        // stage A/B chunk: 128 rows x 128B, SW128-swizzled
#pragma unroll
        for (int i = 0; i < 4; i++) {
            int p = tid + i * 256;               // 0..1023
            int row = p >> 3, c16 = p & 7;
            uint32_t sw = SW128((uint32_t)(row * 128 + c16 * 16));
            *(uint4*)(sA + sw) =
                *(const uint4*)(g_Xb + (size_t)(bm + row) * D + kc * 64 + c16 * 8);
            *(uint4*)(sB + sw) =
                *(const uint4*)(g_Yb + (size_t)(bn + row) * D + kc * 64 + c16 * 8);
        }
        __syncthreads();

#pragma unroll
        for (int ks = 0; ks < 4; ks++) {         // 4 x K=16 per chunk
            uint32_t kbyte = ks * 32;
            uint32_t af[2][4];
#pragma unroll
            for (int mt = 0; mt < 2; mt++) {
                uint32_t byte = (uint32_t)((aRow + mt * 16) * 128) + kbyte + aSeg * 16;
                ldsm_x4(sA_base + SW128(byte), af[mt][0], af[mt][1], af[mt][2], af[mt][3]);
            }
            uint32_t bf[4][4];
#pragma unroll
            for (int np = 0; np < 4; np++) {
                uint32_t byte = (uint32_t)((bRow + np * 16) * 128) + kbyte + bSeg * 16;
                ldsm_x4(sB_base + SW128(byte), bf[np][0], bf[np][1], bf[np][2], bf[np][3]);
            }
#pragma unroll
            for (int mt = 0; mt < 2; mt++)
#pragma unroll
                for (int nt = 0; nt < 8; nt++)
                    mma_16816(acc[mt][nt], af[mt],
                              bf[nt >> 1][(nt & 1) * 2], bf[nt >> 1][(nt & 1) * 2 + 1]);
        }
    }

    // epilogue: cost = clamp(xs + ys - 2*dot, 0); K = exp(-cost/REG) -> bf16
    int g = lane >> 2, tig = lane & 3;
#pragma unroll
    for (int mt = 0; mt < 2; mt++) {
        int r0l = wm * 32 + mt * 16 + g;
        int r1l = r0l + 8;
        float xs0 = s_xs[r0l], xs1 = s_xs[r1l];
#pragma unroll
        for (int nt = 0; nt < 8; nt++) {
            int cl = wn * 64 + nt * 8 + 2 * tig;
            float ys0 = s_ys[cl], ys1 = s_ys[cl + 1];
            float c00 = fmaxf(xs0 + ys0 - 2.0f * acc[mt][nt][0], 0.0f);
            float c01 = fmaxf(xs0 + ys1 - 2.0f * acc[mt][nt][1], 0.0f);
            float c10 = fmaxf(xs1 + ys0 - 2.0f * acc[mt][nt][2], 0.0f);
            float c11 = fmaxf(xs1 + ys1 - 2.0f * acc[mt][nt][3], 0.0f);
            __nv_bfloat162 k0 = __floats2bfloat162_rn(__expf(-c00 * INV_REG),
                                                      __expf(-c01 * INV_REG));
            __nv_bfloat162 k1 = __floats2bfloat162_rn(__expf(-c10 * INV_REG),
                                                      __expf(-c11 * INV_REG));
            *(__nv_bfloat162*)(g_K + (size_t)(bm + r0l) * N + bn + cl) = k0;
            *(__nv_bfloat162*)(g_K + (size_t)(bm + r1l) * N + bn + cl) = k1;
        }
    }
}

// -------- kernel 3: PERSISTENT Sinkhorn loop (packed f32x2 math) --------
__global__ void __launch_bounds__(256) sinkhorn_kernel() {
    __shared__ float red[RG][8];
    __shared__ float ush[RG];
    __shared__ float vred[8][32];
    int tid  = threadIdx.x;
    int lane = tid & 31, wid = tid >> 5;
    int base = blockIdx.x * ROWS_PER_BLOCK;

    for (int it = 0; it < ITERS; ++it) {
        unsigned long long vlk[8];
        const unsigned long long* vg = (const unsigned long long*)g_v;
#pragma unroll
        for (int q = 0; q < 8; q++) vlk[q] = __ldcg(&vg[tid * 8 + q]);

        unsigned long long vpk[8];
#pragma unroll
        for (int q = 0; q < 8; q++) vpk[q] = 0ULL;

        uint4 raw[RG][2];
        unsigned long long fc[RG][8];
#pragma unroll
        for (int r = 0; r < RG; r++) {
            const uint4* kr = (const uint4*)(g_K + (size_t)(base + r) * N);
            raw[r][0] = __ldg(&kr[2 * tid]);
            raw[r][1] = __ldg(&kr[2 * tid + 1]);
        }
#pragma unroll
        for (int r = 0; r < RG; r++) {
            const unsigned* w = (const unsigned*)&raw[r][0];
#pragma unroll
            for (int q = 0; q < 8; q++) fc[r][q] = bf2_f32x2(w[q]);
        }

        for (int g0 = 0; g0 < ROWS_PER_BLOCK; g0 += RG) {
            if (g0 + RG < ROWS_PER_BLOCK) {
#pragma unroll
                for (int r = 0; r < RG; r++) {
                    const uint4* kr = (const uint4*)(g_K + (size_t)(base + g0 + RG + r) * N);
                    raw[r][0] = __ldg(&kr[2 * tid]);
                    raw[r][1] = __ldg(&kr[2 * tid + 1]);
                }
            }
            float dot[RG];
#pragma unroll
            for (int r = 0; r < RG; r++) {
                unsigned long long dacc = 0ULL;
#pragma unroll
                for (int q = 0; q < 8; q++) {
                    asm("fma.rn.f32x2 %0, %1, %2, %0;"
                        : "+l"(dacc) : "l"(fc[r][q]), "l"(vlk[q]));
                }
                float dlo, dhi;
                asm("mov.b64 {%0, %1}, %2;" : "=f"(dlo), "=f"(dhi) : "l"(dacc));
                dot[r] = dlo + dhi;
            }
#pragma unroll
            for (int r = 0; r < RG; r++) {
                float s = dot[r];
#pragma unroll
                for (int o = 16; o; o >>= 1) s += __shfl_down_sync(0xffffffffu, s, o);
                if (lane == 0) red[r][wid] = s;
            }
            __syncthreads();
            if (tid < RG) {
                float s = 0.0f;
#pragma unroll
                for (int w = 0; w < 8; w++) s += red[tid][w];
                float u = AB / (s + EPS);
                ush[tid] = u;
                g_u[base + g0 + tid] = u;
            }
            __syncthreads();
#pragma unroll
            for (int r = 0; r < RG; r++) {
                unsigned long long u2;
                asm("mov.b64 %0, {%1, %1};" : "=l"(u2) : "f"(ush[r]));
#pragma unroll
                for (int q = 0; q < 8; q++) {
                    asm("fma.rn.f32x2 %0, %1, %2, %0;"
                        : "+l"(vpk[q]) : "l"(fc[r][q]), "l"(u2));
                }
            }
            if (g0 + RG < ROWS_PER_BLOCK) {
#pragma unroll
                for (int r = 0; r < RG; r++) {
                    const unsigned* w = (const unsigned*)&raw[r][0];
#pragma unroll
                    for (int q = 0; q < 8; q++) fc[r][q] = bf2_f32x2(w[q]);
                }
            }
        }
        unsigned long long* pp =
            (unsigned long long*)(g_vpart + (size_t)blockIdx.x * N + tid * 16);
#pragma unroll
        for (int q = 0; q < 8; q++) pp[q] = vpk[q];

        grid_barrier();

        {
            int jj = tid & 31, bg = tid >> 5;
            int j = blockIdx.x * 32 + jj;
            float s = 0.0f;
#pragma unroll
            for (int k = 0; k < BLOCKS_UV / 8; k++) {
                int b = bg * (BLOCKS_UV / 8) + k;
                s += __ldcg(&g_vpart[(size_t)b * N + j]);
            }
            vred[bg][jj] = s;
            __syncthreads();
            if (tid < 32) {
                float t = 0.0f;
#pragma unroll
                for (int w = 0; w < 8; w++) t += vred[w][tid];
                g_v[blockIdx.x * 32 + tid] = AB / (t + EPS);
            }
        }

        grid_barrier();
    }
}

// -------- kernel 4: per-row loss partials --------
__global__ void __launch_bounds__(256) loss_part_kernel() {
    int i = blockIdx.x, tid = threadIdx.x;
    float ui = g_u[i];
    const uint4*  krow = (const uint4*)(g_K + (size_t)i * N);
    const float2* vv   = (const float2*)g_v;
    float s = 0.0f;
#pragma unroll
    for (int half = 0; half < 2; half++) {
        int q = half * 256 + tid;
        uint4 kb = krow[q];
        float2 f0 = __bfloat1622float2(*(__nv_bfloat162*)&kb.x);
        float2 f1 = __bfloat1622float2(*(__nv_bfloat162*)&kb.y);
        float2 f2 = __bfloat1622float2(*(__nv_bfloat162*)&kb.z);
        float2 f3 = __bfloat1622float2(*(__nv_bfloat162*)&kb.w);
        int j2 = q * 4;
        float2 v0 = vv[j2], v1 = vv[j2 + 1], v2 = vv[j2 + 2], v3 = vv[j2 + 3];
        float kf[8] = {f0.x, f0.y, f1.x, f1.y, f2.x, f2.y, f3.x, f3.y};
        float vf[8] = {v0.x, v0.y, v1.x, v1.y, v2.x, v2.y, v3.x, v3.y};
#pragma unroll
        for (int e = 0; e < 8; e++) {
            float cost = fmaxf(-REG * __logf(kf[e]), 0.0f);
            s += kf[e] * vf[e] * cost;
        }
    }
    s = blockReduceSum(s);
    if (tid == 0) g_losspart[i] = ui * s;
}

// -------- kernel 5: final deterministic reduction --------
__global__ void loss_fin_kernel(float* __restrict__ out) {
    float s = 0.0f;
    for (int i = threadIdx.x; i < N; i += 256) s += g_losspart[i];
    s = blockReduceSum(s);
    if (threadIdx.x == 0) out[0] = s;
}

// -------- launch --------
extern "C" void kernel_launch(void* const* d_in, const int* in_sizes, int n_in,
                              void* d_out, int out_size) {
    const float* X = (const float*)d_in[0];  // audio_features [4096,512]
    const float* Y = (const float*)d_in[1];  // text_features  [4096,512]
    float* out = (float*)d_out;

    norms_init_kernel<<<2 * N, 128>>>(X, Y);
    k_gemm_kernel<<<dim3(32, 32), 256>>>();
    sinkhorn_kernel<<<BLOCKS_UV, 256>>>();
    loss_part_kernel<<<N, 256>>>();
    loss_fin_kernel<<<1, 256>>>(out);
}

// round 7
// speedup vs baseline: 1.3842x; 1.0015x over previous
#include <cuda_runtime.h>
#include <cuda_bf16.h>
#include <cstdint>

#define N 4096
#define D 512
#define ITERS 50
#define REG 0.05f
#define INV_REG 20.0f
#define EPS 1e-9f
#define AB (1.0f/4096.0f)
#define VTOL 1e-5f

#define BLOCKS_UV 128
#define ROWS_PER_BLOCK (N / BLOCKS_UV)   // 32
#define RG 4                              // rows per group (prefetch depth)

// -------- scratch (device globals: allocation-free contract) --------
__device__ __nv_bfloat16 g_K[(size_t)N * N];        // 32 MB bf16 kernel matrix
__device__ __nv_bfloat16 g_Xb[(size_t)N * D];       // 4 MB bf16 X
__device__ __nv_bfloat16 g_Yb[(size_t)N * D];       // 4 MB bf16 Y
__device__ float         g_u[N];
__device__ float         g_v[N];
__device__ float         g_vpart[BLOCKS_UV * N];    // 2 MB partials (deterministic)
__device__ float         g_Xs[N];
__device__ float         g_Ys[N];
__device__ float         g_lossblk[BLOCKS_UV];
__device__ unsigned      g_bar_count;
__device__ unsigned      g_bar_gen;
__device__ unsigned      g_ncv[2];                  // convergence flags (dbl-buffered)

// -------- helpers --------
#define SW128(b) ((b) ^ (((b) >> 3) & 0x70))

__device__ __forceinline__ uint32_t smem_u32(const void* p) {
    uint32_t a;
    asm("{ .reg .u64 t; cvta.to.shared.u64 t, %1; cvt.u32.u64 %0, t; }"
        : "=r"(a) : "l"(p));
    return a;
}

__device__ __forceinline__ void ldsm_x4(uint32_t addr, uint32_t& r0, uint32_t& r1,
                                        uint32_t& r2, uint32_t& r3) {
    asm volatile("ldmatrix.sync.aligned.m8n8.x4.shared.b16 {%0,%1,%2,%3}, [%4];"
                 : "=r"(r0), "=r"(r1), "=r"(r2), "=r"(r3) : "r"(addr));
}

__device__ __forceinline__ void mma_16816(float* c, const uint32_t* a,
                                          uint32_t b0, uint32_t b1) {
    asm volatile(
        "mma.sync.aligned.m16n8k16.row.col.f32.bf16.bf16.f32 "
        "{%0,%1,%2,%3}, {%4,%5,%6,%7}, {%8,%9}, {%0,%1,%2,%3};"
        : "+f"(c[0]), "+f"(c[1]), "+f"(c[2]), "+f"(c[3])
        : "r"(a[0]), "r"(a[1]), "r"(a[2]), "r"(a[3]), "r"(b0), "r"(b1));
}

__device__ __forceinline__ float blockReduceSum(float val) {
    __shared__ float sh[32];
    int lane = threadIdx.x & 31;
    int wid  = threadIdx.x >> 5;
#pragma unroll
    for (int o = 16; o; o >>= 1) val += __shfl_down_sync(0xffffffffu, val, o);
    if (lane == 0) sh[wid] = val;
    __syncthreads();
    int nw = (blockDim.x + 31) >> 5;
    val = (threadIdx.x < nw) ? sh[threadIdx.x] : 0.0f;
    if (wid == 0) {
#pragma unroll
        for (int o = 16; o; o >>= 1) val += __shfl_down_sync(0xffffffffu, val, o);
    }
    return val;
}

__device__ __forceinline__ unsigned long long bf2_f32x2(unsigned w) {
    unsigned lo = w << 16;
    unsigned hi = w & 0xffff0000u;
    unsigned long long d;
    asm("mov.b64 %0, {%1, %2};" : "=l"(d) : "r"(lo), "r"(hi));
    return d;
}

// grid barrier, cooperative-groups style: acquire/release on thread 0 only
__device__ __forceinline__ void grid_barrier() {
    __syncthreads();
    if (threadIdx.x == 0) {
        unsigned gen;
        asm volatile("ld.acquire.gpu.global.u32 %0, [%1];"
                     : "=r"(gen) : "l"(&g_bar_gen));
        unsigned old;
        asm volatile("atom.release.gpu.global.add.u32 %0, [%1], %2;"
                     : "=r"(old) : "l"(&g_bar_count), "r"(1u));
        if (old == BLOCKS_UV - 1) {
            asm volatile("st.relaxed.gpu.global.u32 [%0], %1;"
                         :: "l"(&g_bar_count), "r"(0u));
            asm volatile("red.release.gpu.global.add.u32 [%0], %1;"
                         :: "l"(&g_bar_gen), "r"(1u));
        } else {
            unsigned cur;
            do {
                asm volatile("ld.acquire.gpu.global.u32 %0, [%1];"
                             : "=r"(cur) : "l"(&g_bar_gen));
            } while (cur == gen);
        }
    }
    __syncthreads();
}

// -------- kernel 1: norms + bf16 conversion + v<-1 + flag init --------
__global__ void norms_init_kernel(const float* __restrict__ X,
                                  const float* __restrict__ Y) {
    int row = blockIdx.x;  // 0..8191
    if (row == 0 && threadIdx.x == 0) {
        g_bar_count = 0;
        g_ncv[0] = 0;
        g_ncv[1] = 0;
    }
    bool isX = (row < N);
    int r = isX ? row : row - N;
    const float* src = isX ? (X + (size_t)r * D) : (Y + (size_t)r * D);
    float4 t = ((const float4*)src)[threadIdx.x];  // 128 thr * 4 = 512
    __nv_bfloat162 b0 = __floats2bfloat162_rn(t.x, t.y);
    __nv_bfloat162 b1 = __floats2bfloat162_rn(t.z, t.w);
    __nv_bfloat16* dst = isX ? g_Xb : g_Yb;
    uint2 packed = make_uint2(*(unsigned*)&b0, *(unsigned*)&b1);
    *(uint2*)(dst + (size_t)r * D + threadIdx.x * 4) = packed;
    float s = t.x * t.x + t.y * t.y + t.z * t.z + t.w * t.w;
    s = blockReduceSum(s);
    if (threadIdx.x == 0) {
        if (isX) g_Xs[r] = s;
        else     g_Ys[r] = s;
    }
    if (row < 32) g_v[row * 128 + threadIdx.x] = 1.0f;
}

// -------- kernel 2: bf16 HMMA GEMM -> K = exp(-cost/REG) --------
__global__ void __launch_bounds__(256)
k_gemm_kernel() {
    __shared__ __align__(1024) unsigned char sA[128 * 128];
    __shared__ __align__(1024) unsigned char sB[128 * 128];
    __shared__ float s_ys[128];
    __shared__ float s_xs[128];

    int tid = threadIdx.x;
    int lane = tid & 31, w = tid >> 5;
    int wm = w & 3, wn = w >> 2;          // warp coords: 4 x 2
    int bm = blockIdx.y * 128, bn = blockIdx.x * 128;

    if (tid < 128) s_ys[tid] = g_Ys[bn + tid];
    else           s_xs[tid - 128] = g_Xs[bm + tid - 128];

    uint32_t sA_base = smem_u32(sA);
    uint32_t sB_base = smem_u32(sB);

    float acc[2][8][4];
#pragma unroll
    for (int mt = 0; mt < 2; mt++)
#pragma unroll
        for (int nt = 0; nt < 8; nt++)
#pragma unroll
            for (int q = 0; q < 4; q++) acc[mt][nt][q] = 0.0f;

    int aRow = wm * 32 + (lane & 15);
    int aSeg = (lane >> 4) & 1;
    int bRow = wn * 64 + (lane & 7) + ((lane >> 4) & 1) * 8;
    int bSeg = (lane >> 3) & 1;

    for (int kc = 0; kc < 8; kc++) {
        if (kc) __syncthreads();
#pragma unroll
        for (int i = 0; i < 4; i++) {
            int p = tid + i * 256;
            int row = p >> 3, c16 = p & 7;
            uint32_t sw = SW128((uint32_t)(row * 128 + c16 * 16));
            *(uint4*)(sA + sw) =
                *(const uint4*)(g_Xb + (size_t)(bm + row) * D + kc * 64 + c16 * 8);
            *(uint4*)(sB + sw) =
                *(const uint4*)(g_Yb + (size_t)(bn + row) * D + kc * 64 + c16 * 8);
        }
        __syncthreads();

#pragma unroll
        for (int ks = 0; ks < 4; ks++) {
            uint32_t kbyte = ks * 32;
            uint32_t af[2][4];
#pragma unroll
            for (int mt = 0; mt < 2; mt++) {
                uint32_t byte = (uint32_t)((aRow + mt * 16) * 128) + kbyte + aSeg * 16;
                ldsm_x4(sA_base + SW128(byte), af[mt][0], af[mt][1], af[mt][2], af[mt][3]);
            }
            uint32_t bf[4][4];
#pragma unroll
            for (int np = 0; np < 4; np++) {
                uint32_t byte = (uint32_t)((bRow + np * 16) * 128) + kbyte + bSeg * 16;
                ldsm_x4(sB_base + SW128(byte), bf[np][0], bf[np][1], bf[np][2], bf[np][3]);
            }
#pragma unroll
            for (int mt = 0; mt < 2; mt++)
#pragma unroll
                for (int nt = 0; nt < 8; nt++)
                    mma_16816(acc[mt][nt], af[mt],
                              bf[nt >> 1][(nt & 1) * 2], bf[nt >> 1][(nt & 1) * 2 + 1]);
        }
    }

    int g = lane >> 2, tig = lane & 3;
#pragma unroll
    for (int mt = 0; mt < 2; mt++) {
        int r0l = wm * 32 + mt * 16 + g;
        int r1l = r0l + 8;
        float xs0 = s_xs[r0l], xs1 = s_xs[r1l];
#pragma unroll
        for (int nt = 0; nt < 8; nt++) {
            int cl = wn * 64 + nt * 8 + 2 * tig;
            float ys0 = s_ys[cl], ys1 = s_ys[cl + 1];
            float c00 = fmaxf(xs0 + ys0 - 2.0f * acc[mt][nt][0], 0.0f);
            float c01 = fmaxf(xs0 + ys1 - 2.0f * acc[mt][nt][1], 0.0f);
            float c10 = fmaxf(xs1 + ys0 - 2.0f * acc[mt][nt][2], 0.0f);
            float c11 = fmaxf(xs1 + ys1 - 2.0f * acc[mt][nt][3], 0.0f);
            __nv_bfloat162 k0 = __floats2bfloat162_rn(__expf(-c00 * INV_REG),
                                                      __expf(-c01 * INV_REG));
            __nv_bfloat162 k1 = __floats2bfloat162_rn(__expf(-c10 * INV_REG),
                                                      __expf(-c11 * INV_REG));
            *(__nv_bfloat162*)(g_K + (size_t)(bm + r0l) * N + bn + cl) = k0;
            *(__nv_bfloat162*)(g_K + (size_t)(bm + r1l) * N + bn + cl) = k1;
        }
    }
}

// -------- kernel 3: PERSISTENT Sinkhorn + early exit + fused loss --------
__global__ void __launch_bounds__(256) sinkhorn_kernel(float* __restrict__ out) {
    __shared__ float red[RG][8];
    __shared__ float ush[RG];
    __shared__ float vred[8][32];
    __shared__ float lacc[ROWS_PER_BLOCK];
    __shared__ unsigned sflag;
    int tid  = threadIdx.x;
    int lane = tid & 31, wid = tid >> 5;
    int base = blockIdx.x * ROWS_PER_BLOCK;

    for (int it = 0; it < ITERS; ++it) {
        // ---- Phase A: u for own rows + register v-partials ----
        unsigned long long vlk[8];
        const unsigned long long* vg = (const unsigned long long*)g_v;
#pragma unroll
        for (int q = 0; q < 8; q++) vlk[q] = __ldcg(&vg[tid * 8 + q]);

        unsigned long long vpk[8];
#pragma unroll
        for (int q = 0; q < 8; q++) vpk[q] = 0ULL;

        uint4 raw[RG][2];
        unsigned long long fc[RG][8];
#pragma unroll
        for (int r = 0; r < RG; r++) {
            const uint4* kr = (const uint4*)(g_K + (size_t)(base + r) * N);
            raw[r][0] = __ldg(&kr[2 * tid]);
            raw[r][1] = __ldg(&kr[2 * tid + 1]);
        }
#pragma unroll
        for (int r = 0; r < RG; r++) {
            const unsigned* wv = (const unsigned*)&raw[r][0];
#pragma unroll
            for (int q = 0; q < 8; q++) fc[r][q] = bf2_f32x2(wv[q]);
        }

        for (int g0 = 0; g0 < ROWS_PER_BLOCK; g0 += RG) {
            if (g0 + RG < ROWS_PER_BLOCK) {
#pragma unroll
                for (int r = 0; r < RG; r++) {
                    const uint4* kr = (const uint4*)(g_K + (size_t)(base + g0 + RG + r) * N);
                    raw[r][0] = __ldg(&kr[2 * tid]);
                    raw[r][1] = __ldg(&kr[2 * tid + 1]);
                }
            }
            float dot[RG];
#pragma unroll
            for (int r = 0; r < RG; r++) {
                unsigned long long dacc = 0ULL;
#pragma unroll
                for (int q = 0; q < 8; q++) {
                    asm("fma.rn.f32x2 %0, %1, %2, %0;"
                        : "+l"(dacc) : "l"(fc[r][q]), "l"(vlk[q]));
                }
                float dlo, dhi;
                asm("mov.b64 {%0, %1}, %2;" : "=f"(dlo), "=f"(dhi) : "l"(dacc));
                dot[r] = dlo + dhi;
            }
#pragma unroll
            for (int r = 0; r < RG; r++) {
                float s = dot[r];
#pragma unroll
                for (int o = 16; o; o >>= 1) s += __shfl_down_sync(0xffffffffu, s, o);
                if (lane == 0) red[r][wid] = s;
            }
            __syncthreads();
            if (tid < RG) {
                float s = 0.0f;
#pragma unroll
                for (int w = 0; w < 8; w++) s += red[tid][w];
                float u = AB / (s + EPS);
                ush[tid] = u;
                g_u[base + g0 + tid] = u;
            }
            __syncthreads();
#pragma unroll
            for (int r = 0; r < RG; r++) {
                unsigned long long u2;
                asm("mov.b64 %0, {%1, %1};" : "=l"(u2) : "f"(ush[r]));
#pragma unroll
                for (int q = 0; q < 8; q++) {
                    asm("fma.rn.f32x2 %0, %1, %2, %0;"
                        : "+l"(vpk[q]) : "l"(fc[r][q]), "l"(u2));
                }
            }
            if (g0 + RG < ROWS_PER_BLOCK) {
#pragma unroll
                for (int r = 0; r < RG; r++) {
                    const unsigned* wv = (const unsigned*)&raw[r][0];
#pragma unroll
                    for (int q = 0; q < 8; q++) fc[r][q] = bf2_f32x2(wv[q]);
                }
            }
        }
        unsigned long long* pp =
            (unsigned long long*)(g_vpart + (size_t)blockIdx.x * N + tid * 16);
#pragma unroll
        for (int q = 0; q < 8; q++) pp[q] = vpk[q];

        grid_barrier();

        // ---- Phase B: v for own 32 columns + convergence detection ----
        {
            int jj = tid & 31, bg = tid >> 5;
            int j = blockIdx.x * 32 + jj;
            float s = 0.0f;
#pragma unroll
            for (int k = 0; k < BLOCKS_UV / 8; k++) {
                int b = bg * (BLOCKS_UV / 8) + k;
                s += __ldcg(&g_vpart[(size_t)b * N + j]);
            }
            vred[bg][jj] = s;
            __syncthreads();
            if (tid < 32) {
                float t = 0.0f;
#pragma unroll
                for (int w = 0; w < 8; w++) t += vred[w][tid];
                int j2 = blockIdx.x * 32 + tid;
                float vnew = AB / (t + EPS);
                float vold = g_v[j2];
                g_v[j2] = vnew;
                bool big = fabsf(vnew - vold) > VTOL * fabsf(vnew);
                unsigned m = __ballot_sync(0xffffffffu, big);
                if (tid == 0) {
                    if (m)
                        asm volatile("red.relaxed.gpu.global.or.b32 [%0], %1;"
                                     :: "l"(&g_ncv[it & 1]), "r"(1u));
                    asm volatile("st.relaxed.gpu.global.u32 [%0], %1;"
                                 :: "l"(&g_ncv[(it + 1) & 1]), "r"(0u));
                }
            }
        }

        grid_barrier();

        // ---- early exit if every v element converged ----
        if (tid == 0) {
            unsigned f;
            asm volatile("ld.relaxed.gpu.global.u32 %0, [%1];"
                         : "=r"(f) : "l"(&g_ncv[it & 1]));
            sflag = f;
        }
        __syncthreads();
        if (sflag == 0) break;
    }

    // ---- fused loss: sum_i u_i * sum_j K_ij v_j cost_ij over own rows ----
    {
        float vloc[16];
        const float4* vg4 = (const float4*)g_v;
#pragma unroll
        for (int q = 0; q < 4; q++) {
            float4 t = __ldcg(&vg4[tid * 4 + q]);
            vloc[q * 4 + 0] = t.x; vloc[q * 4 + 1] = t.y;
            vloc[q * 4 + 2] = t.z; vloc[q * 4 + 3] = t.w;
        }
        for (int g0 = 0; g0 < ROWS_PER_BLOCK; g0 += RG) {
            float ls[RG];
#pragma unroll
            for (int r = 0; r < RG; r++) {
                const uint4* kr = (const uint4*)(g_K + (size_t)(base + g0 + r) * N);
                uint4 a = __ldg(&kr[2 * tid]);
                uint4 b = __ldg(&kr[2 * tid + 1]);
                const __nv_bfloat162* kp0 = (const __nv_bfloat162*)&a;
                const __nv_bfloat162* kp1 = (const __nv_bfloat162*)&b;
                float s = 0.0f;
#pragma unroll
                for (int q = 0; q < 4; q++) {
                    float2 f = __bfloat1622float2(kp0[q]);
                    float c0 = fmaxf(-REG * __logf(f.x), 0.0f);
                    float c1 = fmaxf(-REG * __logf(f.y), 0.0f);
                    s += f.x * vloc[2 * q] * c0 + f.y * vloc[2 * q + 1] * c1;
                }
#pragma unroll
                for (int q = 0; q < 4; q++) {
                    float2 f = __bfloat1622float2(kp1[q]);
                    float c0 = fmaxf(-REG * __logf(f.x), 0.0f);
                    float c1 = fmaxf(-REG * __logf(f.y), 0.0f);
                    s += f.x * vloc[8 + 2 * q] * c0 + f.y * vloc[8 + 2 * q + 1] * c1;
                }
                ls[r] = s;
            }
#pragma unroll
            for (int r = 0; r < RG; r++) {
                float s = ls[r];
#pragma unroll
                for (int o = 16; o; o >>= 1) s += __shfl_down_sync(0xffffffffu, s, o);
                if (lane == 0) red[r][wid] = s;
            }
            __syncthreads();
            if (tid < RG) {
                float s = 0.0f;
#pragma unroll
                for (int w = 0; w < 8; w++) s += red[tid][w];
                lacc[g0 + tid] = g_u[base + g0 + tid] * s;
            }
            __syncthreads();
        }
        if (tid == 0) {
            float s = 0.0f;
#pragma unroll
            for (int r = 0; r < ROWS_PER_BLOCK; r++) s += lacc[r];
            g_lossblk[blockIdx.x] = s;
        }
    }

    grid_barrier();

    // ---- block 0: final deterministic reduction ----
    if (blockIdx.x == 0) {
        float v = (tid < BLOCKS_UV) ? __ldcg(&g_lossblk[tid]) : 0.0f;
        v = blockReduceSum(v);
        if (tid == 0) out[0] = v;
    }
}

// -------- launch --------
extern "C" void kernel_launch(void* const* d_in, const int* in_sizes, int n_in,
                              void* d_out, int out_size) {
    const float* X = (const float*)d_in[0];  // audio_features [4096,512]
    const float* Y = (const float*)d_in[1];  // text_features  [4096,512]
    float* out = (float*)d_out;

    norms_init_kernel<<<2 * N, 128>>>(X, Y);
    k_gemm_kernel<<<dim3(32, 32), 256>>>();
    sinkhorn_kernel<<<BLOCKS_UV, 256>>>(out);
}

// round 8
// speedup vs baseline: 1.5954x; 1.1526x over previous
#include <cuda_runtime.h>
#include <cuda_bf16.h>
#include <cstdint>

#define N 4096
#define D 512
#define ITERS 50
#define REG 0.05f
#define INV_REG 20.0f
#define EPS 1e-9f
#define AB (1.0f/4096.0f)
#define VTOL 1e-5f

#define BLOCKS_UV 128
#define ROWS_PER_BLOCK (N / BLOCKS_UV)   // 32
#define RG 8                              // rows per group
#define NGRP (ROWS_PER_BLOCK / RG)        // 4 groups

// -------- scratch (device globals: allocation-free contract) --------
__device__ __nv_bfloat16 g_K[(size_t)N * N];        // 32 MB bf16 kernel matrix
__device__ __nv_bfloat16 g_Xb[(size_t)N * D];       // 4 MB bf16 X
__device__ __nv_bfloat16 g_Yb[(size_t)N * D];       // 4 MB bf16 Y
__device__ float         g_u[N];
__device__ float         g_v[N];
__device__ float         g_vpart[BLOCKS_UV * N];    // 2 MB partials (deterministic)
__device__ float         g_Xs[N];
__device__ float         g_Ys[N];
__device__ float         g_lossblk[BLOCKS_UV];
__device__ unsigned      g_bar_count;
__device__ unsigned      g_bar_gen;
__device__ unsigned      g_ncv[2];                  // convergence flags (dbl-buffered)

// -------- helpers --------
#define SW128(b) ((b) ^ (((b) >> 3) & 0x70))

__device__ __forceinline__ uint32_t smem_u32(const void* p) {
    uint32_t a;
    asm("{ .reg .u64 t; cvta.to.shared.u64 t, %1; cvt.u32.u64 %0, t; }"
        : "=r"(a) : "l"(p));
    return a;
}

__device__ __forceinline__ void ldsm_x4(uint32_t addr, uint32_t& r0, uint32_t& r1,
                                        uint32_t& r2, uint32_t& r3) {
    asm volatile("ldmatrix.sync.aligned.m8n8.x4.shared.b16 {%0,%1,%2,%3}, [%4];"
                 : "=r"(r0), "=r"(r1), "=r"(r2), "=r"(r3) : "r"(addr));
}

__device__ __forceinline__ void mma_16816(float* c, const uint32_t* a,
                                          uint32_t b0, uint32_t b1) {
    asm volatile(
        "mma.sync.aligned.m16n8k16.row.col.f32.bf16.bf16.f32 "
        "{%0,%1,%2,%3}, {%4,%5,%6,%7}, {%8,%9}, {%0,%1,%2,%3};"
        : "+f"(c[0]), "+f"(c[1]), "+f"(c[2]), "+f"(c[3])
        : "r"(a[0]), "r"(a[1]), "r"(a[2]), "r"(a[3]), "r"(b0), "r"(b1));
}

__device__ __forceinline__ float blockReduceSum(float val) {
    __shared__ float sh[32];
    int lane = threadIdx.x & 31;
    int wid  = threadIdx.x >> 5;
#pragma unroll
    for (int o = 16; o; o >>= 1) val += __shfl_down_sync(0xffffffffu, val, o);
    if (lane == 0) sh[wid] = val;
    __syncthreads();
    int nw = (blockDim.x + 31) >> 5;
    val = (threadIdx.x < nw) ? sh[threadIdx.x] : 0.0f;
    if (wid == 0) {
#pragma unroll
        for (int o = 16; o; o >>= 1) val += __shfl_down_sync(0xffffffffu, val, o);
    }
    return val;
}

__device__ __forceinline__ unsigned long long bf2_f32x2(unsigned w) {
    unsigned lo = w << 16;
    unsigned hi = w & 0xffff0000u;
    unsigned long long d;
    asm("mov.b64 %0, {%1, %2};" : "=l"(d) : "r"(lo), "r"(hi));
    return d;
}

// grid barrier, cooperative-groups style: acquire/release on thread 0 only
__device__ __forceinline__ void grid_barrier() {
    __syncthreads();
    if (threadIdx.x == 0) {
        unsigned gen;
        asm volatile("ld.acquire.gpu.global.u32 %0, [%1];"
                     : "=r"(gen) : "l"(&g_bar_gen));
        unsigned old;
        asm volatile("atom.release.gpu.global.add.u32 %0, [%1], %2;"
                     : "=r"(old) : "l"(&g_bar_count), "r"(1u));
        if (old == BLOCKS_UV - 1) {
            asm volatile("st.relaxed.gpu.global.u32 [%0], %1;"
                         :: "l"(&g_bar_count), "r"(0u));
            asm volatile("red.release.gpu.global.add.u32 [%0], %1;"
                         :: "l"(&g_bar_gen), "r"(1u));
        } else {
            unsigned cur;
            do {
                asm volatile("ld.acquire.gpu.global.u32 %0, [%1];"
                             : "=r"(cur) : "l"(&g_bar_gen));
            } while (cur == gen);
        }
    }
    __syncthreads();
}

// -------- kernel 1: norms + bf16 conversion + v<-1 + flag init --------
__global__ void norms_init_kernel(const float* __restrict__ X,
                                  const float* __restrict__ Y) {
    int row = blockIdx.x;  // 0..8191
    if (row == 0 && threadIdx.x == 0) {
        g_bar_count = 0;
        g_ncv[0] = 0;
        g_ncv[1] = 0;
    }
    bool isX = (row < N);
    int r = isX ? row : row - N;
    const float* src = isX ? (X + (size_t)r * D) : (Y + (size_t)r * D);
    float4 t = ((const float4*)src)[threadIdx.x];  // 128 thr * 4 = 512
    __nv_bfloat162 b0 = __floats2bfloat162_rn(t.x, t.y);
    __nv_bfloat162 b1 = __floats2bfloat162_rn(t.z, t.w);
    __nv_bfloat16* dst = isX ? g_Xb : g_Yb;
    uint2 packed = make_uint2(*(unsigned*)&b0, *(unsigned*)&b1);
    *(uint2*)(dst + (size_t)r * D + threadIdx.x * 4) = packed;
    float s = t.x * t.x + t.y * t.y + t.z * t.z + t.w * t.w;
    s = blockReduceSum(s);
    if (threadIdx.x == 0) {
        if (isX) g_Xs[r] = s;
        else     g_Ys[r] = s;
    }
    if (row < 32) g_v[row * 128 + threadIdx.x] = 1.0f;
}

// -------- kernel 2: bf16 HMMA GEMM -> K = exp(-cost/REG) --------
__global__ void __launch_bounds__(256)
k_gemm_kernel() {
    __shared__ __align__(1024) unsigned char sA[128 * 128];
    __shared__ __align__(1024) unsigned char sB[128 * 128];
    __shared__ float s_ys[128];
    __shared__ float s_xs[128];

    int tid = threadIdx.x;
    int lane = tid & 31, w = tid >> 5;
    int wm = w & 3, wn = w >> 2;          // warp coords: 4 x 2
    int bm = blockIdx.y * 128, bn = blockIdx.x * 128;

    if (tid < 128) s_ys[tid] = g_Ys[bn + tid];
    else           s_xs[tid - 128] = g_Xs[bm + tid - 128];

    uint32_t sA_base = smem_u32(sA);
    uint32_t sB_base = smem_u32(sB);

    float acc[2][8][4];
#pragma unroll
    for (int mt = 0; mt < 2; mt++)
#pragma unroll
        for (int nt = 0; nt < 8; nt++)
#pragma unroll
            for (int q = 0; q < 4; q++) acc[mt][nt][q] = 0.0f;

    int aRow = wm * 32 + (lane & 15);
    int aSeg = (lane >> 4) & 1;
    int bRow = wn * 64 + (lane & 7) + ((lane >> 4) & 1) * 8;
    int bSeg = (lane >> 3) & 1;

    for (int kc = 0; kc < 8; kc++) {
        if (kc) __syncthreads();
#pragma unroll
        for (int i = 0; i < 4; i++) {
            int p = tid + i * 256;
            int row = p >> 3, c16 = p & 7;
            uint32_t sw = SW128((uint32_t)(row * 128 + c16 * 16));
            *(uint4*)(sA + sw) =
                *(const uint4*)(g_Xb + (size_t)(bm + row) * D + kc * 64 + c16 * 8);
            *(uint4*)(sB + sw) =
                *(const uint4*)(g_Yb + (size_t)(bn + row) * D + kc * 64 + c16 * 8);
        }
        __syncthreads();

#pragma unroll
        for (int ks = 0; ks < 4; ks++) {
            uint32_t kbyte = ks * 32;
            uint32_t af[2][4];
#pragma unroll
            for (int mt = 0; mt < 2; mt++) {
                uint32_t byte = (uint32_t)((aRow + mt * 16) * 128) + kbyte + aSeg * 16;
                ldsm_x4(sA_base + SW128(byte), af[mt][0], af[mt][1], af[mt][2], af[mt][3]);
            }
            uint32_t bf[4][4];
#pragma unroll
            for (int np = 0; np < 4; np++) {
                uint32_t byte = (uint32_t)((bRow + np * 16) * 128) + kbyte + bSeg * 16;
                ldsm_x4(sB_base + SW128(byte), bf[np][0], bf[np][1], bf[np][2], bf[np][3]);
            }
#pragma unroll
            for (int mt = 0; mt < 2; mt++)
#pragma unroll
                for (int nt = 0; nt < 8; nt++)
                    mma_16816(acc[mt][nt], af[mt],
                              bf[nt >> 1][(nt & 1) * 2], bf[nt >> 1][(nt & 1) * 2 + 1]);
        }
    }

    int g = lane >> 2, tig = lane & 3;
#pragma unroll
    for (int mt = 0; mt < 2; mt++) {
        int r0l = wm * 32 + mt * 16 + g;
        int r1l = r0l + 8;
        float xs0 = s_xs[r0l], xs1 = s_xs[r1l];
#pragma unroll
        for (int nt = 0; nt < 8; nt++) {
            int cl = wn * 64 + nt * 8 + 2 * tig;
            float ys0 = s_ys[cl], ys1 = s_ys[cl + 1];
            float c00 = fmaxf(xs0 + ys0 - 2.0f * acc[mt][nt][0], 0.0f);
            float c01 = fmaxf(xs0 + ys1 - 2.0f * acc[mt][nt][1], 0.0f);
            float c10 = fmaxf(xs1 + ys0 - 2.0f * acc[mt][nt][2], 0.0f);
            float c11 = fmaxf(xs1 + ys1 - 2.0f * acc[mt][nt][3], 0.0f);
            __nv_bfloat162 k0 = __floats2bfloat162_rn(__expf(-c00 * INV_REG),
                                                      __expf(-c01 * INV_REG));
            __nv_bfloat162 k1 = __floats2bfloat162_rn(__expf(-c10 * INV_REG),
                                                      __expf(-c11 * INV_REG));
            *(__nv_bfloat162*)(g_K + (size_t)(bm + r0l) * N + bn + cl) = k0;
            *(__nv_bfloat162*)(g_K + (size_t)(bm + r1l) * N + bn + cl) = k1;
        }
    }
}

// -------- kernel 3: PERSISTENT Sinkhorn + early exit + fused loss --------
// Column ownership: thread t owns cols [8t, 8t+8) and [2048+8t, 2048+8t+8)
// -> every LDG.128 on a K row is fully coalesced (512B/warp contiguous).
// Phase A per group of 8 rows: stream loads, per-thread dots, butterfly
// shfl reduce (bit-exact, all lanes), ONE syncthreads (double-buffered red),
// per-lane u computation broadcast by shfl -> vp accumulation.
__global__ void __launch_bounds__(256) sinkhorn_kernel(float* __restrict__ out) {
    __shared__ __align__(16) float red[2][8][8];   // [buf][row][warp]
    __shared__ float vred[8][32];
    __shared__ float lacc[ROWS_PER_BLOCK];
    __shared__ unsigned sflag;
    int tid  = threadIdx.x;
    int lane = tid & 31, wid = tid >> 5;
    int base = blockIdx.x * ROWS_PER_BLOCK;

    for (int it = 0; it < ITERS; ++it) {
        // ---- Phase A ----
        unsigned long long vlk[8];
        const unsigned long long* vg = (const unsigned long long*)g_v;
#pragma unroll
        for (int q = 0; q < 4; q++) {
            vlk[q]     = __ldcg(&vg[tid * 4 + q]);          // cols 8t+2q,+1
            vlk[4 + q] = __ldcg(&vg[1024 + tid * 4 + q]);   // cols 2048+8t+2q,+1
        }
        unsigned long long vpk[8];
#pragma unroll
        for (int q = 0; q < 8; q++) vpk[q] = 0ULL;

        uint4 buf[2][RG][2];
#pragma unroll
        for (int r = 0; r < RG; r++) {
            const uint4* kr = (const uint4*)(g_K + (size_t)(base + r) * N);
            buf[0][r][0] = __ldg(&kr[tid]);         // cols 8t..8t+7
            buf[0][r][1] = __ldg(&kr[256 + tid]);   // cols 2048+8t..
        }

#pragma unroll
        for (int g = 0; g < NGRP; g++) {
            const int cb = g & 1, nb = cb ^ 1;
            if (g + 1 < NGRP) {
#pragma unroll
                for (int r = 0; r < RG; r++) {
                    const uint4* kr =
                        (const uint4*)(g_K + (size_t)(base + (g + 1) * RG + r) * N);
                    buf[nb][r][0] = __ldg(&kr[tid]);
                    buf[nb][r][1] = __ldg(&kr[256 + tid]);
                }
            }
            // per-thread dots over owned 16 cols
            float dot[RG];
#pragma unroll
            for (int r = 0; r < RG; r++) {
                unsigned long long dacc = 0ULL;
                const unsigned* w0 = (const unsigned*)&buf[cb][r][0];
#pragma unroll
                for (int q = 0; q < 4; q++) {
                    unsigned long long f = bf2_f32x2(w0[q]);
                    asm("fma.rn.f32x2 %0, %1, %2, %0;"
                        : "+l"(dacc) : "l"(f), "l"(vlk[q]));
                }
                const unsigned* w1 = (const unsigned*)&buf[cb][r][1];
#pragma unroll
                for (int q = 0; q < 4; q++) {
                    unsigned long long f = bf2_f32x2(w1[q]);
                    asm("fma.rn.f32x2 %0, %1, %2, %0;"
                        : "+l"(dacc) : "l"(f), "l"(vlk[4 + q]));
                }
                float dlo, dhi;
                asm("mov.b64 {%0, %1}, %2;" : "=f"(dlo), "=f"(dhi) : "l"(dacc));
                dot[r] = dlo + dhi;
            }
            // butterfly reduce: all lanes end with the warp total (bit-exact)
#pragma unroll
            for (int r = 0; r < RG; r++) {
#pragma unroll
                for (int o = 16; o; o >>= 1)
                    dot[r] += __shfl_xor_sync(0xffffffffu, dot[r], o);
            }
            if (lane < 8) red[cb][lane][wid] = dot[lane];
            __syncthreads();
            // lanes 0-7 (every warp) compute u for the 8 rows
            float uval = 0.0f;
            if (lane < 8) {
                float4 p0 = *(float4*)&red[cb][lane][0];
                float4 p1 = *(float4*)&red[cb][lane][4];
                float s = ((p0.x + p0.y) + (p0.z + p0.w)) +
                          ((p1.x + p1.y) + (p1.z + p1.w));
                uval = AB / (s + EPS);
                if (wid == 0) g_u[base + g * RG + lane] = uval;
            }
            // vp accumulation
#pragma unroll
            for (int r = 0; r < RG; r++) {
                float ur = __shfl_sync(0xffffffffu, uval, r);
                unsigned long long u2;
                asm("mov.b64 %0, {%1, %1};" : "=l"(u2) : "f"(ur));
                const unsigned* w0 = (const unsigned*)&buf[cb][r][0];
#pragma unroll
                for (int q = 0; q < 4; q++) {
                    unsigned long long f = bf2_f32x2(w0[q]);
                    asm("fma.rn.f32x2 %0, %1, %2, %0;"
                        : "+l"(vpk[q]) : "l"(f), "l"(u2));
                }
                const unsigned* w1 = (const unsigned*)&buf[cb][r][1];
#pragma unroll
                for (int q = 0; q < 4; q++) {
                    unsigned long long f = bf2_f32x2(w1[q]);
                    asm("fma.rn.f32x2 %0, %1, %2, %0;"
                        : "+l"(vpk[4 + q]) : "l"(f), "l"(u2));
                }
            }
        }
        // write partials (u64 index c == float cols 2c,2c+1)
        {
            unsigned long long* pp =
                (unsigned long long*)g_vpart + (size_t)blockIdx.x * (N / 2);
#pragma unroll
            for (int q = 0; q < 4; q++) {
                pp[tid * 4 + q] = vpk[q];
                pp[1024 + tid * 4 + q] = vpk[4 + q];
            }
        }

        grid_barrier();

        // ---- Phase B: v for own 32 columns + convergence detection ----
        {
            int jj = tid & 31, bg = tid >> 5;
            int j = blockIdx.x * 32 + jj;
            float s = 0.0f;
#pragma unroll
            for (int k = 0; k < BLOCKS_UV / 8; k++) {
                int b = bg * (BLOCKS_UV / 8) + k;
                s += __ldcg(&g_vpart[(size_t)b * N + j]);
            }
            vred[bg][jj] = s;
            __syncthreads();
            if (tid < 32) {
                float t = 0.0f;
#pragma unroll
                for (int w = 0; w < 8; w++) t += vred[w][tid];
                int j2 = blockIdx.x * 32 + tid;
                float vnew = AB / (t + EPS);
                float vold = g_v[j2];
                g_v[j2] = vnew;
                bool big = fabsf(vnew - vold) > VTOL * fabsf(vnew);
                unsigned m = __ballot_sync(0xffffffffu, big);
                if (tid == 0) {
                    if (m)
                        asm volatile("red.relaxed.gpu.global.or.b32 [%0], %1;"
                                     :: "l"(&g_ncv[it & 1]), "r"(1u));
                    asm volatile("st.relaxed.gpu.global.u32 [%0], %1;"
                                 :: "l"(&g_ncv[(it + 1) & 1]), "r"(0u));
                }
            }
        }

        grid_barrier();

        if (tid == 0) {
            unsigned f;
            asm volatile("ld.relaxed.gpu.global.u32 %0, [%1];"
                         : "=r"(f) : "l"(&g_ncv[it & 1]));
            sflag = f;
        }
        __syncthreads();
        if (sflag == 0) break;
    }

    // ---- fused loss: sum_i u_i * sum_j K_ij v_j cost_ij over own rows ----
    {
        float vloc[16];
        const float4* vg4 = (const float4*)g_v;
#pragma unroll
        for (int q = 0; q < 2; q++) {
            float4 t = __ldcg(&vg4[tid * 2 + q]);
            vloc[q * 4 + 0] = t.x; vloc[q * 4 + 1] = t.y;
            vloc[q * 4 + 2] = t.z; vloc[q * 4 + 3] = t.w;
            float4 t2 = __ldcg(&vg4[512 + tid * 2 + q]);
            vloc[8 + q * 4 + 0] = t2.x; vloc[8 + q * 4 + 1] = t2.y;
            vloc[8 + q * 4 + 2] = t2.z; vloc[8 + q * 4 + 3] = t2.w;
        }
#pragma unroll
        for (int g = 0; g < NGRP; g++) {
            const int cb = g & 1;
            float ls[RG];
#pragma unroll
            for (int r = 0; r < RG; r++) {
                const uint4* kr =
                    (const uint4*)(g_K + (size_t)(base + g * RG + r) * N);
                uint4 a = __ldg(&kr[tid]);
                uint4 b = __ldg(&kr[256 + tid]);
                const __nv_bfloat162* kp0 = (const __nv_bfloat162*)&a;
                const __nv_bfloat162* kp1 = (const __nv_bfloat162*)&b;
                float s = 0.0f;
#pragma unroll
                for (int q = 0; q < 4; q++) {
                    float2 f = __bfloat1622float2(kp0[q]);
                    float c0 = fmaxf(-REG * __logf(f.x), 0.0f);
                    float c1 = fmaxf(-REG * __logf(f.y), 0.0f);
                    s += f.x * vloc[2 * q] * c0 + f.y * vloc[2 * q + 1] * c1;
                }
#pragma unroll
                for (int q = 0; q < 4; q++) {
                    float2 f = __bfloat1622float2(kp1[q]);
                    float c0 = fmaxf(-REG * __logf(f.x), 0.0f);
                    float c1 = fmaxf(-REG * __logf(f.y), 0.0f);
                    s += f.x * vloc[8 + 2 * q] * c0 + f.y * vloc[8 + 2 * q + 1] * c1;
                }
                ls[r] = s;
            }
#pragma unroll
            for (int r = 0; r < RG; r++) {
#pragma unroll
                for (int o = 16; o; o >>= 1)
                    ls[r] += __shfl_xor_sync(0xffffffffu, ls[r], o);
            }
            if (lane < 8) red[cb][lane][wid] = ls[lane];
            __syncthreads();
            if (wid == 0 && lane < 8) {
                float4 p0 = *(float4*)&red[cb][lane][0];
                float4 p1 = *(float4*)&red[cb][lane][4];
                float s = ((p0.x + p0.y) + (p0.z + p0.w)) +
                          ((p1.x + p1.y) + (p1.z + p1.w));
                lacc[g * RG + lane] = g_u[base + g * RG + lane] * s;
            }
            __syncthreads();
        }
        if (tid == 0) {
            float s = 0.0f;
#pragma unroll
            for (int r = 0; r < ROWS_PER_BLOCK; r++) s += lacc[r];
            g_lossblk[blockIdx.x] = s;
        }
    }

    grid_barrier();

    if (blockIdx.x == 0) {
        float v = (tid < BLOCKS_UV) ? __ldcg(&g_lossblk[tid]) : 0.0f;
        v = blockReduceSum(v);
        if (tid == 0) out[0] = v;
    }
}

// -------- launch --------
extern "C" void kernel_launch(void* const* d_in, const int* in_sizes, int n_in,
                              void* d_out, int out_size) {
    const float* X = (const float*)d_in[0];  // audio_features [4096,512]
    const float* Y = (const float*)d_in[1];  // text_features  [4096,512]
    float* out = (float*)d_out;

    norms_init_kernel<<<2 * N, 128>>>(X, Y);
    k_gemm_kernel<<<dim3(32, 32), 256>>>();
    sinkhorn_kernel<<<BLOCKS_UV, 256>>>(out);
}